// round 3
// baseline (speedup 1.0000x reference)
#include <cuda_runtime.h>
#include <math.h>

// ---------------------------------------------------------------------------
// QNetBlock: 18-qubit state-vector sim, batch 32.
//   state = P2 * D2 * P1 * D1 * x ;  out = |state| / ||x||
//   D = tensor product of per-wire 2x2 Rot unitaries (butterflies per bit)
//   P = CNOT ring = GF(2)-linear permutation of the 18-bit index (XOR masks)
// Wire w <-> index bit (17-w)  (bit 0 = LSB, stride 1).
// ---------------------------------------------------------------------------

#define NB      32
#define NBITS   18
#define NSTATE  (1 << NBITS)      // 262144
#define CHUNK   8192              // 2^13
#define NCHUNK  32                // 2^5

__device__ float2 g_sa[(size_t)NB * NSTATE];   // 64 MB ping
__device__ float2 g_sb[(size_t)NB * NSTATE];   // 64 MB pong
__device__ float  g_partial[NB * NCHUNK];
__device__ float  g_invnorm[NB];

struct PermM { unsigned m[18]; };  // columns of the GF(2)-linear CNOT-ring map

// smem swizzle: conflict-free for all three ownership access patterns
__device__ __forceinline__ int sw(int i) {
    return (i & ~31) | ((i ^ (i >> 5)) & 31);
}

// Rot(phi, theta, omega) = RZ(omega) RY(theta) RZ(phi)
__device__ __forceinline__ void make_gate(const float* __restrict__ p, float2* u) {
    float phi = p[0], th = p[1], om = p[2];
    float c, s;
    sincosf(0.5f * th, &s, &c);
    float a  = 0.5f * (phi + om);
    float bb = 0.5f * (phi - om);
    float sa, ca, sb, cb;
    sincosf(a,  &sa, &ca);
    sincosf(bb, &sb, &cb);
    u[0] = make_float2( ca * c, -sa * c);   // e^{-i(phi+om)/2} cos
    u[1] = make_float2(-cb * s, -sb * s);   // -e^{ i(phi-om)/2} sin
    u[2] = make_float2( cb * s, -sb * s);   //  e^{-i(phi-om)/2} sin
    u[3] = make_float2( ca * c,  sa * c);   //  e^{ i(phi+om)/2} cos
}

__device__ __forceinline__ void bfly(float2& A, float2& B,
                                     float2 u00, float2 u01, float2 u10, float2 u11) {
    float2 a = A, b = B;
    A.x = u00.x * a.x - u00.y * a.y + u01.x * b.x - u01.y * b.y;
    A.y = u00.x * a.y + u00.y * a.x + u01.x * b.y + u01.y * b.x;
    B.x = u10.x * a.x - u10.y * a.y + u11.x * b.x - u11.y * b.y;
    B.y = u10.x * a.y + u10.y * a.x + u11.x * b.y + u11.y * b.x;
}

// ---------------------------------------------------------------------------
// pass_low: gates on bits 0..12 (wires 5..17) of one layer.
// CTA = one contiguous 8192-amp chunk. 256 threads, 32 amps in registers each.
// Ownership A: bits 8..12 (direct coalesced global load) -> 5 levels
// Ownership B: bits 0..4  (via smem transpose)           -> 5 levels
// Ownership C: bits 5..9  (via smem transpose)           -> levels 5..7,
//              then direct coalesced global store.
// FIRST: reads float x, also emits deterministic per-chunk sum(x^2).
// ---------------------------------------------------------------------------
template<bool FIRST>
__global__ void __launch_bounds__(256, 2)
pass_low(const float* __restrict__ x, const float* __restrict__ params)
{
    extern __shared__ float2 smem[];     // 8192 float2 = 64 KB
    __shared__ float2 Us[13][4];
    __shared__ float  wsum[8];

    int t  = threadIdx.x;
    int b  = blockIdx.x >> 5;
    int ch = blockIdx.x & 31;
    int base = b * NSTATE + ch * CHUNK;

    if (t < 13) make_gate(params + (17 - t) * 3, Us[t]);  // Us[p] = gate for bit p

    float2 v[32];
    if (FIRST) {
        float ss = 0.f;
#pragma unroll
        for (int k = 0; k < 32; k++) {
            float xv = x[base + t + 256 * k];
            v[k] = make_float2(xv, 0.f);
            ss += xv * xv;
        }
#pragma unroll
        for (int o = 16; o; o >>= 1) ss += __shfl_down_sync(0xffffffffu, ss, o);
        if ((t & 31) == 0) wsum[t >> 5] = ss;
    } else {
#pragma unroll
        for (int k = 0; k < 32; k++) v[k] = g_sb[base + t + 256 * k];
    }
    __syncthreads();   // gates + wsum ready
    if (FIRST && t == 0) {
        float s = 0.f;
        for (int i = 0; i < 8; i++) s += wsum[i];
        g_partial[blockIdx.x] = s;   // deterministic fixed-order reduction
    }

    // Ownership A: elem = t + 256*k  -> k bits are elem bits 8..12
#pragma unroll
    for (int kb = 0; kb < 5; kb++) {
        int m = 1 << kb;
        float2 u00 = Us[8 + kb][0], u01 = Us[8 + kb][1],
               u10 = Us[8 + kb][2], u11 = Us[8 + kb][3];
#pragma unroll
        for (int k = 0; k < 32; k++)
            if (!(k & m)) bfly(v[k], v[k + m], u00, u01, u10, u11);
    }
#pragma unroll
    for (int k = 0; k < 32; k++) smem[sw(t + 256 * k)] = v[k];
    __syncthreads();

    // Ownership B: elem = t*32 + k -> k bits are elem bits 0..4
#pragma unroll
    for (int k = 0; k < 32; k++) v[k] = smem[sw(t * 32 + k)];
#pragma unroll
    for (int kb = 0; kb < 5; kb++) {
        int m = 1 << kb;
        float2 u00 = Us[kb][0], u01 = Us[kb][1], u10 = Us[kb][2], u11 = Us[kb][3];
#pragma unroll
        for (int k = 0; k < 32; k++)
            if (!(k & m)) bfly(v[k], v[k + m], u00, u01, u10, u11);
    }
#pragma unroll
    for (int k = 0; k < 32; k++) smem[sw(t * 32 + k)] = v[k];
    __syncthreads();

    // Ownership C: elem = r + 32*k + 1024*h -> k bits are elem bits 5..9
    int r = t & 31, h = t >> 5;
#pragma unroll
    for (int k = 0; k < 32; k++) v[k] = smem[sw(r + 32 * k + 1024 * h)];
#pragma unroll
    for (int kb = 0; kb < 3; kb++) {   // bits 5,6,7 (8,9 already done in A)
        int m = 1 << kb;
        float2 u00 = Us[5 + kb][0], u01 = Us[5 + kb][1],
               u10 = Us[5 + kb][2], u11 = Us[5 + kb][3];
#pragma unroll
        for (int k = 0; k < 32; k++)
            if (!(k & m)) bfly(v[k], v[k + m], u00, u01, u10, u11);
    }
#pragma unroll
    for (int k = 0; k < 32; k++)       // coalesced: lanes (r) contiguous
        g_sa[base + r + 32 * k + 1024 * h] = v[k];
}

// ---------------------------------------------------------------------------
// pass_high: gates on bits 13..17 (wires 0..4) of one layer, then the CNOT-ring
// permutation folded into the store as an XOR-mask scatter.
// Thread owns 32 amps at stride 2^13 (bits 13..17); lanes = contiguous bits 0..4
// -> every load instruction is a coalesced 256B warp read. No smem tile needed.
// LAST: writes |amp| * invnorm to the float output instead of the state buffer.
// ---------------------------------------------------------------------------
template<bool LAST>
__global__ void __launch_bounds__(256, 2)
pass_high(const float* __restrict__ params, PermM P, float* __restrict__ outF)
{
    __shared__ float2 Us[5][4];
    int t = threadIdx.x;
    if (t < 5) make_gate(params + (4 - t) * 3, Us[t]);  // Us[kb] = gate for bit 13+kb
    __syncthreads();

    int lane = t & 31, warp = t >> 5;
    int b    = blockIdx.x >> 5;
    int col  = (blockIdx.x & 31) * 8 + warp;   // bits 5..12
    int off  = (col << 5) | lane;              // bits 0..12
    int base = b * NSTATE + off;

    float2 v[32];
#pragma unroll
    for (int k = 0; k < 32; k++) v[k] = g_sa[base + (k << 13)];

#pragma unroll
    for (int kb = 0; kb < 5; kb++) {
        int m = 1 << kb;
        float2 u00 = Us[kb][0], u01 = Us[kb][1], u10 = Us[kb][2], u11 = Us[kb][3];
#pragma unroll
        for (int k = 0; k < 32; k++)
            if (!(k & m)) bfly(v[k], v[k + m], u00, u01, u10, u11);
    }

    // Permutation target base from low 13 bits (GF(2)-linear -> XOR of columns)
    unsigned tb = 0;
#pragma unroll
    for (int p = 0; p < 13; p++)
        tb ^= P.m[p] & (0u - (unsigned)((off >> p) & 1));
    unsigned m13 = P.m[13], m14 = P.m[14], m15 = P.m[15],
             m16 = P.m[16], m17 = P.m[17];
    int bb = b * NSTATE;

    if (!LAST) {
#pragma unroll
        for (int k = 0; k < 32; k++) {
            unsigned tg = tb;
            if (k & 1)  tg ^= m13;
            if (k & 2)  tg ^= m14;
            if (k & 4)  tg ^= m15;
            if (k & 8)  tg ^= m16;
            if (k & 16) tg ^= m17;
            g_sb[bb + tg] = v[k];
        }
    } else {
        float inv = g_invnorm[b];
#pragma unroll
        for (int k = 0; k < 32; k++) {
            unsigned tg = tb;
            if (k & 1)  tg ^= m13;
            if (k & 2)  tg ^= m14;
            if (k & 4)  tg ^= m15;
            if (k & 8)  tg ^= m16;
            if (k & 16) tg ^= m17;
            float2 a = v[k];
            outF[bb + tg] = sqrtf(a.x * a.x + a.y * a.y) * inv;
        }
    }
}

__global__ void norm_kernel() {
    int b = threadIdx.x;
    if (b < NB) {
        float s = 0.f;
        for (int i = 0; i < NCHUNK; i++) s += g_partial[b * NCHUNK + i];
        g_invnorm[b] = 1.0f / sqrtf(s);
    }
}

// ---------------------------------------------------------------------------
// Host side
// ---------------------------------------------------------------------------
static PermM makePerm(int l) {
    // scatter target = F18(F17(...F1(i))): apply CNOTs in loop order to a basis
    // index. Linear over GF(2) -> precompute columns.
    PermM P;
    for (int p = 0; p < 18; p++) {
        unsigned idx = 1u << p;
        for (int i = 0; i < 18; i++) {
            int c  = (i + l) % 18;
            int t  = (i + l + 1) % 18;
            int cb = 17 - c;
            int tb = 17 - t;
            idx ^= ((idx >> cb) & 1u) << tb;
        }
        P.m[p] = idx;
    }
    return P;
}

extern "C" void kernel_launch(void* const* d_in, const int* in_sizes, int n_in,
                              void* d_out, int out_size)
{
    const float* x      = (const float*)d_in[0];
    const float* params = (const float*)d_in[1];
    if (n_in >= 2 && in_sizes[0] < in_sizes[1]) {  // defensive input-order guard
        x      = (const float*)d_in[1];
        params = (const float*)d_in[0];
    }

    cudaFuncSetAttribute(pass_low<true>,
                         cudaFuncAttributeMaxDynamicSharedMemorySize, CHUNK * 8);
    cudaFuncSetAttribute(pass_low<false>,
                         cudaFuncAttributeMaxDynamicSharedMemorySize, CHUNK * 8);

    PermM P0 = makePerm(0);
    PermM P1 = makePerm(1);

    // Layer 0
    pass_low<true> <<<NB * NCHUNK, 256, CHUNK * 8>>>(x, params);
    norm_kernel    <<<1, 32>>>();
    pass_high<false><<<NB * 32, 256>>>(params, P0, nullptr);
    // Layer 1
    pass_low<false><<<NB * NCHUNK, 256, CHUNK * 8>>>(nullptr, params + 18 * 3);
    pass_high<true> <<<NB * 32, 256>>>(params + 18 * 3, P1, (float*)d_out);
}